// round 9
// baseline (speedup 1.0000x reference)
#include <cuda_runtime.h>
#include <stdint.h>

#define B_IMG   16
#define H_IMG   1024
#define W_IMG   1024
#define WORDS   32                   // 32-bit words per 1024-px row
#define R_STRIP 8                    // output rows per warp in scatter kernel
#define HALO    5
#define SROWS   (R_STRIP + 2 * HALO) // 18 rows held in registers

// 2 MB packed bitmap scratch — L2-resident between kernels.
__device__ uint32_t g_packed[B_IMG * H_IMG * WORDS];

// spread 8 bits (b0..b7) to positions 0,4,8,...,28
__device__ __forceinline__ uint32_t spread4(uint32_t x) {
    x &= 0xFFu;
    x = (x | (x << 12)) & 0x000F000Fu;
    x = (x | (x << 6))  & 0x03030303u;
    x = (x | (x << 3))  & 0x11111111u;
    return x;
}

// ---------------------------------------------------------------------------
// Kernel A: pack 64 MB of {0,1} floats into a 2 MB bitmap.
// Each warp packs 1024 consecutive floats -> 32 words (1 per lane).
// ---------------------------------------------------------------------------
__global__ __launch_bounds__(256)
void pack_kernel(const float* __restrict__ in) {
    const int lane = threadIdx.x & 31;
    const int wg   = (blockIdx.x * blockDim.x + threadIdx.x) >> 5; // 0..16383

    const float4* src = reinterpret_cast<const float4*>(in) + (size_t)wg * 256;
    float4 v[8];
#pragma unroll
    for (int i = 0; i < 8; ++i)
        v[i] = __ldcs(&src[i * 32 + lane]);  // coalesced, 8 in flight

    uint32_t b0 = 0, b1 = 0, b2 = 0, b3 = 0;
#pragma unroll
    for (int k = 0; k < 8; ++k) {
        const uint32_t t0 = __ballot_sync(0xFFFFFFFFu, v[k].x != 0.0f);
        const uint32_t t1 = __ballot_sync(0xFFFFFFFFu, v[k].y != 0.0f);
        const uint32_t t2 = __ballot_sync(0xFFFFFFFFu, v[k].z != 0.0f);
        const uint32_t t3 = __ballot_sync(0xFFFFFFFFu, v[k].w != 0.0f);
        if ((lane >> 2) == k) { b0 = t0; b1 = t1; b2 = t2; b3 = t3; }
    }
    const int s = (lane & 3) * 8;
    const uint32_t w = spread4(b0 >> s)
                     | (spread4(b1 >> s) << 1)
                     | (spread4(b2 >> s) << 2)
                     | (spread4(b3 >> s) << 3);
    g_packed[(size_t)wg * 32 + lane] = w;    // coalesced 128B per warp
}

// ---------------------------------------------------------------------------
// Kernel F: fill the entire output with 1.0f. Pure dependency-free store
// stream (8 independent streaming STG.128 per thread).
// ---------------------------------------------------------------------------
__global__ __launch_bounds__(256)
void fill_ones_kernel(float* __restrict__ out) {
    const float4 ONES = make_float4(1.0f, 1.0f, 1.0f, 1.0f);
    float4* dst = reinterpret_cast<float4*>(out)
                + (size_t)blockIdx.x * 2048 + threadIdx.x;
#pragma unroll
    for (int i = 0; i < 8; ++i)
        __stcs(&dst[i * 256], ONES);         // coalesced, 8 in flight
}

// ---------------------------------------------------------------------------
// Kernel B: register dilation + sparse zero-scatter.
// Lane l holds word l of each of 18 rows; 5 dilation iterations with batched
// cross-lane carries (2 shfls/iter). Output pixels are ~99.84% ones (already
// written by fill); only the ~26k zero pixels get stored here.
// ---------------------------------------------------------------------------
__global__ __launch_bounds__(256)
void dilate_scatter_kernel(float* __restrict__ out) {
    const int lane  = threadIdx.x & 31;
    const int wg    = (blockIdx.x * blockDim.x + threadIdx.x) >> 5; // 0..2047
    const int img   = wg >> 7;            // 128 strips per image
    const int strip = wg & 127;
    const int r0    = strip * R_STRIP;

    const uint32_t* pimg = g_packed + (size_t)img * H_IMG * WORDS;

    uint32_t m[SROWS];
#pragma unroll
    for (int r = 0; r < SROWS; ++r) {
        const int gr = r0 - HALO + r;
        m[r] = (gr >= 0 && gr < H_IMG) ? pimg[gr * WORDS + lane] : 0u;
    }

#pragma unroll
    for (int it = 0; it < 5; ++it) {
        uint32_t Lb = 0u, Rb = 0u;
#pragma unroll
        for (int r = 0; r < SROWS; ++r) {
            Lb |= (m[r] >> 31) << r;       // bit31 of row r -> bit r
            Rb |= (m[r] & 1u) << r;        // bit0  of row r -> bit r
        }
        uint32_t lw = __shfl_up_sync(0xFFFFFFFFu, Lb, 1);
        uint32_t rw = __shfl_down_sync(0xFFFFFFFFu, Rb, 1);
        if (lane == 0)  lw = 0u;           // image edge: clamp == no-op for OR
        if (lane == 31) rw = 0u;

        uint32_t prev = 0u;
#pragma unroll
        for (int r = 0; r < SROWS; ++r) {
            const uint32_t cur = m[r];
            const uint32_t dn  = (r < SROWS - 1) ? m[r + 1] : 0u;
            m[r] = cur | prev | dn
                 | (cur << 1) | ((lw >> r) & 1u)
                 | (cur >> 1) | (((rw >> r) & 1u) << 31);
            prev = cur;
        }
    }

    // scatter zeros: lane l owns pixels [32l, 32l+32) of each output row
    float* obase = out + (size_t)img * H_IMG * W_IMG + lane * 32;
#pragma unroll
    for (int r = 0; r < R_STRIP; ++r) {
        uint32_t z = ~m[HALO + r];         // zero bits (usually 0)
        if (z) {
            float* orow = obase + (size_t)(r0 + r) * W_IMG;
            do {
                const int b = __ffs(z) - 1;
                orow[b] = 0.0f;
                z &= z - 1u;
            } while (z);
        }
    }
}

extern "C" void kernel_launch(void* const* d_in, const int* in_sizes, int n_in,
                              void* d_out, int out_size) {
    const float* mask = (const float*)d_in[0];   // (16,1,1024,1024) f32, binary
    // d_in[1] = fixed Laplacian-cross weight, d_in[2] = iter_num (=5):
    // the op reduces exactly to 5 iterations of 4-connected binary dilation.
    float* out = (float*)d_out;

    pack_kernel<<<2048, 256>>>(mask);            // 64 MB read -> 2 MB bitmap
    fill_ones_kernel<<<2048, 256>>>(out);        // 64 MB pure store stream
    dilate_scatter_kernel<<<256, 256>>>(out);    // dilation + ~26k zero stores
}

// round 10
// speedup vs baseline: 1.1850x; 1.1850x over previous
#include <cuda_runtime.h>
#include <stdint.h>

#define B_IMG   16
#define H_IMG   1024
#define W_IMG   1024
#define WORDS   32                   // 32-bit words per 1024-px row
#define R_STRIP 8                    // output rows per warp in scatter kernel
#define HALO    5
#define SROWS   (R_STRIP + 2 * HALO) // 18 rows held in registers

// 2 MB packed bitmap scratch — L2-resident between kernels.
__device__ uint32_t g_packed[B_IMG * H_IMG * WORDS];

// spread 8 bits (b0..b7) to positions 0,4,8,...,28
__device__ __forceinline__ uint32_t spread4(uint32_t x) {
    x &= 0xFFu;
    x = (x | (x << 12)) & 0x000F000Fu;
    x = (x | (x << 6))  & 0x03030303u;
    x = (x | (x << 3))  & 0x11111111u;
    return x;
}

// ---------------------------------------------------------------------------
// Kernel 1: fused pack + fill. Each warp:
//   - streams in 1024 input floats (8 x float4 per lane, MLP=8, __ldcs)
//   - ballot-packs them into 32 bitmap words  -> g_packed (L2-resident)
//   - streams out 1024 ones to d_out (__stcs), independent of the loads
// Read and write DRAM streams overlap inside one kernel instead of running
// as two serialized 64 MB passes.
// ---------------------------------------------------------------------------
__global__ __launch_bounds__(256)
void pack_fill_kernel(const float* __restrict__ in, float* __restrict__ out) {
    const int lane = threadIdx.x & 31;
    const int wg   = (blockIdx.x * blockDim.x + threadIdx.x) >> 5; // 0..16383

    const float4 ONES = make_float4(1.0f, 1.0f, 1.0f, 1.0f);
    const float4* src = reinterpret_cast<const float4*>(in)  + (size_t)wg * 256;
    float4*       dst = reinterpret_cast<float4*>(out)       + (size_t)wg * 256;

    // kick off the write stream first (no dependencies at all)
#pragma unroll
    for (int i = 0; i < 8; ++i)
        __stcs(&dst[i * 32 + lane], ONES);   // coalesced, 8 in flight

    float4 v[8];
#pragma unroll
    for (int i = 0; i < 8; ++i)
        v[i] = __ldcs(&src[i * 32 + lane]);  // coalesced, 8 in flight

    uint32_t b0 = 0, b1 = 0, b2 = 0, b3 = 0;
#pragma unroll
    for (int k = 0; k < 8; ++k) {
        const uint32_t t0 = __ballot_sync(0xFFFFFFFFu, v[k].x != 0.0f);
        const uint32_t t1 = __ballot_sync(0xFFFFFFFFu, v[k].y != 0.0f);
        const uint32_t t2 = __ballot_sync(0xFFFFFFFFu, v[k].z != 0.0f);
        const uint32_t t3 = __ballot_sync(0xFFFFFFFFu, v[k].w != 0.0f);
        if ((lane >> 2) == k) { b0 = t0; b1 = t1; b2 = t2; b3 = t3; }
    }
    const int s = (lane & 3) * 8;
    const uint32_t w = spread4(b0 >> s)
                     | (spread4(b1 >> s) << 1)
                     | (spread4(b2 >> s) << 2)
                     | (spread4(b3 >> s) << 3);
    g_packed[(size_t)wg * 32 + lane] = w;    // coalesced 128B per warp
}

// ---------------------------------------------------------------------------
// Kernel 2: register dilation + sparse zero-scatter.
// Lane l holds word l of each of 18 rows; 5 dilation iterations with batched
// cross-lane carries (2 shfls/iter). Output pixels are ~99.84% ones (already
// written by pack_fill); only the ~26k zero pixels get stored here.
// ---------------------------------------------------------------------------
__global__ __launch_bounds__(256)
void dilate_scatter_kernel(float* __restrict__ out) {
    const int lane  = threadIdx.x & 31;
    const int wg    = (blockIdx.x * blockDim.x + threadIdx.x) >> 5; // 0..2047
    const int img   = wg >> 7;            // 128 strips per image
    const int strip = wg & 127;
    const int r0    = strip * R_STRIP;

    const uint32_t* pimg = g_packed + (size_t)img * H_IMG * WORDS;

    uint32_t m[SROWS];
#pragma unroll
    for (int r = 0; r < SROWS; ++r) {
        const int gr = r0 - HALO + r;
        m[r] = (gr >= 0 && gr < H_IMG) ? pimg[gr * WORDS + lane] : 0u;
    }

#pragma unroll
    for (int it = 0; it < 5; ++it) {
        uint32_t Lb = 0u, Rb = 0u;
#pragma unroll
        for (int r = 0; r < SROWS; ++r) {
            Lb |= (m[r] >> 31) << r;       // bit31 of row r -> bit r
            Rb |= (m[r] & 1u) << r;        // bit0  of row r -> bit r
        }
        uint32_t lw = __shfl_up_sync(0xFFFFFFFFu, Lb, 1);
        uint32_t rw = __shfl_down_sync(0xFFFFFFFFu, Rb, 1);
        if (lane == 0)  lw = 0u;           // image edge: clamp == no-op for OR
        if (lane == 31) rw = 0u;

        uint32_t prev = 0u;
#pragma unroll
        for (int r = 0; r < SROWS; ++r) {
            const uint32_t cur = m[r];
            const uint32_t dn  = (r < SROWS - 1) ? m[r + 1] : 0u;
            m[r] = cur | prev | dn
                 | (cur << 1) | ((lw >> r) & 1u)
                 | (cur >> 1) | (((rw >> r) & 1u) << 31);
            prev = cur;
        }
    }

    // scatter zeros: lane l owns pixels [32l, 32l+32) of each output row
    float* obase = out + (size_t)img * H_IMG * W_IMG + lane * 32;
#pragma unroll
    for (int r = 0; r < R_STRIP; ++r) {
        uint32_t z = ~m[HALO + r];         // zero bits (usually 0)
        if (z) {
            float* orow = obase + (size_t)(r0 + r) * W_IMG;
            do {
                const int b = __ffs(z) - 1;
                orow[b] = 0.0f;
                z &= z - 1u;
            } while (z);
        }
    }
}

extern "C" void kernel_launch(void* const* d_in, const int* in_sizes, int n_in,
                              void* d_out, int out_size) {
    const float* mask = (const float*)d_in[0];   // (16,1,1024,1024) f32, binary
    // d_in[1] = fixed Laplacian-cross weight, d_in[2] = iter_num (=5):
    // the op reduces exactly to 5 iterations of 4-connected binary dilation.
    float* out = (float*)d_out;

    pack_fill_kernel<<<2048, 256>>>(mask, out);  // 64 MB in + 64 MB out, overlapped
    dilate_scatter_kernel<<<256, 256>>>(out);    // dilation + ~26k zero stores
}

// round 11
// speedup vs baseline: 1.2046x; 1.0166x over previous
#include <cuda_runtime.h>
#include <stdint.h>

#define B_IMG   16
#define H_IMG   1024
#define W_IMG   1024
#define WORDS   32                   // 32-bit words per 1024-px row
#define HALO    5
#define R_TILE  32                   // output rows per block
#define T_ROWS  (R_TILE + 2 * HALO)  // 42 rows incl. halo
#define SH_W    (WORDS + 2)          // +2 zero guard columns

// spread 8 bits (b0..b7) to positions 0,4,8,...,28
__device__ __forceinline__ uint32_t spread4(uint32_t x) {
    x &= 0xFFu;
    x = (x | (x << 12)) & 0x000F000Fu;
    x = (x | (x << 6))  & 0x03030303u;
    x = (x | (x << 3))  & 0x11111111u;
    return x;
}

// ---------------------------------------------------------------------------
// Fully fused: fill-ones + pack + smem dilation + sparse zero-scatter.
// Block (256 thr, 8 warps) owns 32 output rows of one image.
//   Phase 0: stream 1.0f over its 32 output rows (dep-free store stream)
//   Phase 1: ballot-pack its 42 input rows (halo incl.) into smem bits
//   Phase 2: 5 iterations of 4-connected dilation, ping-pong in smem
//   Phase 3: scatter 0.0f to the ~0.16% zero pixels (block-local rows only)
// The dilation ALU hides under the 148 MB of streaming memory traffic.
// ---------------------------------------------------------------------------
__global__ __launch_bounds__(256)
void dilate_fused_kernel(const float* __restrict__ in, float* __restrict__ out) {
    __shared__ uint32_t sbuf[2][T_ROWS][SH_W];   // 11424 B

    const int tid  = threadIdx.x;
    const int lane = tid & 31;
    const int wid  = tid >> 5;
    const int img  = blockIdx.y;
    const int r0   = blockIdx.x * R_TILE;        // first output row of tile

    const float* ibase = in  + (size_t)img * H_IMG * W_IMG;
    float*       obase = out + (size_t)img * H_IMG * W_IMG;

    // ---- Phase 0: fill ones over this block's 32 output rows ----
    {
        const float4 ONES = make_float4(1.0f, 1.0f, 1.0f, 1.0f);
        float4* dst = reinterpret_cast<float4*>(obase + (size_t)r0 * W_IMG);
#pragma unroll
        for (int i = 0; i < 32; ++i)             // 8192 float4s / 256 thr
            __stcs(&dst[i * 256 + tid], ONES);
    }

    // zero guard columns of both buffers
    for (int r = tid; r < T_ROWS; r += 256) {
        sbuf[0][r][0] = 0u; sbuf[0][r][SH_W - 1] = 0u;
        sbuf[1][r][0] = 0u; sbuf[1][r][SH_W - 1] = 0u;
    }

    // ---- Phase 1: pack 42 rows (each warp packs rows wid, wid+8, ...) ----
    for (int r = wid; r < T_ROWS; r += 8) {
        const int gr = r0 - HALO + r;            // global input row
        uint32_t word = 0u;
        if (gr >= 0 && gr < H_IMG) {             // warp-uniform
            const float4* src =
                reinterpret_cast<const float4*>(ibase + (size_t)gr * W_IMG);
            float4 v[8];
#pragma unroll
            for (int i = 0; i < 8; ++i)
                v[i] = __ldcs(&src[i * 32 + lane]);   // MLP=8, coalesced

            uint32_t b0 = 0, b1 = 0, b2 = 0, b3 = 0;
#pragma unroll
            for (int k = 0; k < 8; ++k) {
                const uint32_t t0 = __ballot_sync(0xFFFFFFFFu, v[k].x != 0.0f);
                const uint32_t t1 = __ballot_sync(0xFFFFFFFFu, v[k].y != 0.0f);
                const uint32_t t2 = __ballot_sync(0xFFFFFFFFu, v[k].z != 0.0f);
                const uint32_t t3 = __ballot_sync(0xFFFFFFFFu, v[k].w != 0.0f);
                if ((lane >> 2) == k) { b0 = t0; b1 = t1; b2 = t2; b3 = t3; }
            }
            const int s = (lane & 3) * 8;
            word = spread4(b0 >> s)
                 | (spread4(b1 >> s) << 1)
                 | (spread4(b2 >> s) << 2)
                 | (spread4(b3 >> s) << 3);
        }
        sbuf[0][r][1 + lane] = word;             // lane -> word index
    }
    __syncthreads();

    // ---- Phase 2: 5 dilation iterations, ping-pong in smem ----
    int cur = 0;
#pragma unroll
    for (int it = 0; it < 5; ++it) {
        const int nxt = cur ^ 1;
#pragma unroll
        for (int base = 0; base < T_ROWS * WORDS; base += 256) {
            const int idx = base + tid;
            if (idx < T_ROWS * WORDS) {          // 1344 words
                const int r = idx >> 5;
                const int w = (idx & 31) + 1;
                const uint32_t c  = sbuf[cur][r][w];
                const uint32_t lw = sbuf[cur][r][w - 1];
                const uint32_t rw = sbuf[cur][r][w + 1];
                const uint32_t up = (r > 0)          ? sbuf[cur][r - 1][w] : 0u;
                const uint32_t dn = (r < T_ROWS - 1) ? sbuf[cur][r + 1][w] : 0u;
                sbuf[nxt][r][w] = c | up | dn
                                | (c << 1) | (lw >> 31)
                                | (c >> 1) | (rw << 31);
            }
        }
        __syncthreads();
        cur = nxt;
    }

    // ---- Phase 3: scatter zeros (~0.16% of pixels) ----
    // 32 rows x 32 words = 1024 words; 4 per thread. Fill of these rows was
    // done by THIS block before the syncthreads above -> ordering safe.
#pragma unroll
    for (int q = 0; q < 4; ++q) {
        const int idx = q * 256 + tid;
        const int r   = idx >> 5;                // output row within tile
        const int w   = idx & 31;
        uint32_t z = ~sbuf[cur][HALO + r][w + 1];
        if (z) {
            float* orow = obase + (size_t)(r0 + r) * W_IMG + w * 32;
            do {
                const int b = __ffs(z) - 1;
                orow[b] = 0.0f;
                z &= z - 1u;
            } while (z);
        }
    }
}

extern "C" void kernel_launch(void* const* d_in, const int* in_sizes, int n_in,
                              void* d_out, int out_size) {
    const float* mask = (const float*)d_in[0];   // (16,1,1024,1024) f32, binary
    // d_in[1] = fixed Laplacian-cross weight, d_in[2] = iter_num (=5):
    // the op reduces exactly to 5 iterations of 4-connected binary dilation.
    float* out = (float*)d_out;

    dim3 grid(H_IMG / R_TILE, B_IMG);            // 32 x 16 = 512 blocks
    dilate_fused_kernel<<<grid, 256>>>(mask, out);
}

// round 12
// speedup vs baseline: 1.3890x; 1.1531x over previous
#include <cuda_runtime.h>
#include <stdint.h>

#define B_IMG   16
#define H_IMG   1024
#define W_IMG   1024
#define WORDS   32                   // 32-bit words per 1024-px row
#define HALO    5
#define R_TILE  32                   // output rows per block
#define T_ROWS  (R_TILE + 2 * HALO)  // 42 rows incl. halo
#define SH_W    (WORDS + 2)          // +2 zero guard columns

// spread 8 bits (b0..b7) to positions 0,4,8,...,28
__device__ __forceinline__ uint32_t spread4(uint32_t x) {
    x &= 0xFFu;
    x = (x | (x << 12)) & 0x000F000Fu;
    x = (x | (x << 6))  & 0x03030303u;
    x = (x | (x << 3))  & 0x11111111u;
    return x;
}

// ---------------------------------------------------------------------------
// Fully fused, stream-interleaved:
//   per warp-iteration: issue 8 pack loads -> issue ~6 fill stores -> ballots.
// Loads (input) and stores (ones to output) are independent, so read and
// write DRAM streams stay concurrently in flight (the R10 pack_fill pattern),
// instead of the block-phase-serialized bursts of R11.
// Then: 5 smem dilation iterations + sparse zero-scatter (~0.16% of pixels).
// ---------------------------------------------------------------------------
__global__ __launch_bounds__(256)
void dilate_fused_kernel(const float* __restrict__ in, float* __restrict__ out) {
    __shared__ uint32_t sbuf[2][T_ROWS][SH_W];   // 11424 B

    const int tid  = threadIdx.x;
    const int lane = tid & 31;
    const int wid  = tid >> 5;
    const int img  = blockIdx.y;
    const int r0   = blockIdx.x * R_TILE;        // first output row of tile

    const float* ibase = in  + (size_t)img * H_IMG * W_IMG;
    float*       obase = out + (size_t)img * H_IMG * W_IMG;

    // zero guard columns of both buffers
    for (int r = tid; r < T_ROWS; r += 256) {
        sbuf[0][r][0] = 0u; sbuf[0][r][SH_W - 1] = 0u;
        sbuf[1][r][0] = 0u; sbuf[1][r][SH_W - 1] = 0u;
    }

    // ---- fused pack + fill, interleaved streams ----
    // Pack: warp handles halo rows r = wid + 8j (j = 0..5, r < 42).
    // Fill: warp owns output rows [wid*4, wid*4+4) = 1024 float4,
    //       lane-sliced as dst4[i*32 + lane], i = 0..31, ~6 per iteration.
    const float4 ONES = make_float4(1.0f, 1.0f, 1.0f, 1.0f);
    float4* fdst = reinterpret_cast<float4*>(obase + (size_t)(r0 + wid * 4) * W_IMG);

#pragma unroll
    for (int j = 0; j < 6; ++j) {
        const int r  = wid + 8 * j;              // halo row index (may be >= 42)
        const int gr = r0 - HALO + r;            // global input row
        const bool rowok = (r < T_ROWS) && (gr >= 0) && (gr < H_IMG);

        // (a) issue pack loads (8 independent LDG.128)
        float4 v[8];
        if (rowok) {                             // warp-uniform
            const float4* src =
                reinterpret_cast<const float4*>(ibase + (size_t)gr * W_IMG);
#pragma unroll
            for (int i = 0; i < 8; ++i)
                v[i] = __ldcs(&src[i * 32 + lane]);
        }

        // (b) issue fill stores (independent of the loads just issued)
#pragma unroll
        for (int i = j * 6; i < j * 6 + 6; ++i)
            if (i < 32)
                __stcs(&fdst[i * 32 + lane], ONES);

        // (c) consume loads via ballots, write packed word to smem
        if (r < T_ROWS) {
            uint32_t word = 0u;
            if (rowok) {
                uint32_t b0 = 0, b1 = 0, b2 = 0, b3 = 0;
#pragma unroll
                for (int k = 0; k < 8; ++k) {
                    const uint32_t t0 = __ballot_sync(0xFFFFFFFFu, v[k].x != 0.0f);
                    const uint32_t t1 = __ballot_sync(0xFFFFFFFFu, v[k].y != 0.0f);
                    const uint32_t t2 = __ballot_sync(0xFFFFFFFFu, v[k].z != 0.0f);
                    const uint32_t t3 = __ballot_sync(0xFFFFFFFFu, v[k].w != 0.0f);
                    if ((lane >> 2) == k) { b0 = t0; b1 = t1; b2 = t2; b3 = t3; }
                }
                const int s = (lane & 3) * 8;
                word = spread4(b0 >> s)
                     | (spread4(b1 >> s) << 1)
                     | (spread4(b2 >> s) << 2)
                     | (spread4(b3 >> s) << 3);
            }
            sbuf[0][r][1 + lane] = word;
        }
    }
    __syncthreads();

    // ---- 5 dilation iterations, ping-pong in smem ----
    int cur = 0;
#pragma unroll
    for (int it = 0; it < 5; ++it) {
        const int nxt = cur ^ 1;
#pragma unroll
        for (int base = 0; base < T_ROWS * WORDS; base += 256) {
            const int idx = base + tid;
            if (idx < T_ROWS * WORDS) {          // 1344 words
                const int r = idx >> 5;
                const int w = (idx & 31) + 1;
                const uint32_t c  = sbuf[cur][r][w];
                const uint32_t lw = sbuf[cur][r][w - 1];
                const uint32_t rw = sbuf[cur][r][w + 1];
                const uint32_t up = (r > 0)          ? sbuf[cur][r - 1][w] : 0u;
                const uint32_t dn = (r < T_ROWS - 1) ? sbuf[cur][r + 1][w] : 0u;
                sbuf[nxt][r][w] = c | up | dn
                                | (c << 1) | (lw >> 31)
                                | (c >> 1) | (rw << 31);
            }
        }
        __syncthreads();
        cur = nxt;
    }

    // ---- scatter zeros (~0.16% of pixels); block already filled its rows ----
#pragma unroll
    for (int q = 0; q < 4; ++q) {
        const int idx = q * 256 + tid;
        const int r   = idx >> 5;                // output row within tile
        const int w   = idx & 31;
        uint32_t z = ~sbuf[cur][HALO + r][w + 1];
        if (z) {
            float* orow = obase + (size_t)(r0 + r) * W_IMG + w * 32;
            do {
                const int b = __ffs(z) - 1;
                orow[b] = 0.0f;
                z &= z - 1u;
            } while (z);
        }
    }
}

extern "C" void kernel_launch(void* const* d_in, const int* in_sizes, int n_in,
                              void* d_out, int out_size) {
    const float* mask = (const float*)d_in[0];   // (16,1,1024,1024) f32, binary
    // d_in[1] = fixed Laplacian-cross weight, d_in[2] = iter_num (=5):
    // the op reduces exactly to 5 iterations of 4-connected binary dilation.
    float* out = (float*)d_out;

    dim3 grid(H_IMG / R_TILE, B_IMG);            // 32 x 16 = 512 blocks
    dilate_fused_kernel<<<grid, 256>>>(mask, out);
}

// round 13
// speedup vs baseline: 1.5125x; 1.0889x over previous
#include <cuda_runtime.h>
#include <stdint.h>

#define B_IMG   16
#define H_IMG   1024
#define W_IMG   1024
#define WORDS   32                   // 32-bit words per 1024-px row
#define HALO    5
#define R_TILE  64                   // output rows per block
#define T_ROWS  (R_TILE + 2 * HALO)  // 74 rows incl. halo
#define SH_W    (WORDS + 2)          // +2 zero guard columns
#define THREADS 512
#define NW      16                   // warps per block

// spread 8 bits (b0..b7) to positions 0,4,8,...,28
__device__ __forceinline__ uint32_t spread4(uint32_t x) {
    x &= 0xFFu;
    x = (x | (x << 12)) & 0x000F000Fu;
    x = (x | (x << 6))  & 0x03030303u;
    x = (x | (x << 3))  & 0x11111111u;
    return x;
}

// ---------------------------------------------------------------------------
// Fully fused, stream-interleaved, wide blocks (16 warps / 64 output rows):
//   per warp-iteration: issue 8 pack loads -> issue 7 fill stores -> ballots.
// 5 rows max per warp (fewer serial DRAM bubbles than 6-row variant), halo
// read amplification 74/64 = 1.16x, 32 warps/SM co-resident, single wave.
// Then: 5 smem dilation iterations + sparse zero-scatter (~0.16% of pixels).
// ---------------------------------------------------------------------------
__global__ __launch_bounds__(THREADS)
void dilate_fused_kernel(const float* __restrict__ in, float* __restrict__ out) {
    __shared__ uint32_t sbuf[2][T_ROWS][SH_W];   // 20128 B

    const int tid  = threadIdx.x;
    const int lane = tid & 31;
    const int wid  = tid >> 5;
    const int img  = blockIdx.y;
    const int r0   = blockIdx.x * R_TILE;        // first output row of tile

    const float* ibase = in  + (size_t)img * H_IMG * W_IMG;
    float*       obase = out + (size_t)img * H_IMG * W_IMG;

    // zero guard columns of both buffers
    for (int r = tid; r < T_ROWS; r += THREADS) {
        sbuf[0][r][0] = 0u; sbuf[0][r][SH_W - 1] = 0u;
        sbuf[1][r][0] = 0u; sbuf[1][r][SH_W - 1] = 0u;
    }

    // ---- fused pack + fill, interleaved streams ----
    // Pack: warp handles halo rows r = wid + 16j (j = 0..4, r < 74).
    // Fill: warp owns output rows [wid*4, wid*4+4) = 1024 float4,
    //       lane-sliced as fdst[i*32 + lane], i = 0..31, 7 per iteration.
    const float4 ONES = make_float4(1.0f, 1.0f, 1.0f, 1.0f);
    float4* fdst = reinterpret_cast<float4*>(obase + (size_t)(r0 + wid * 4) * W_IMG);

#pragma unroll
    for (int j = 0; j < 5; ++j) {
        const int r  = wid + 16 * j;             // halo row index (may be >= 74)
        const int gr = r0 - HALO + r;            // global input row
        const bool rowok = (r < T_ROWS) && (gr >= 0) && (gr < H_IMG);

        // (a) issue pack loads (8 independent LDG.128)
        float4 v[8];
        if (rowok) {                             // warp-uniform
            const float4* src =
                reinterpret_cast<const float4*>(ibase + (size_t)gr * W_IMG);
#pragma unroll
            for (int i = 0; i < 8; ++i)
                v[i] = __ldcs(&src[i * 32 + lane]);
        }

        // (b) issue fill stores (independent of the loads just issued)
#pragma unroll
        for (int i = j * 7; i < j * 7 + 7; ++i)
            if (i < 32)
                __stcs(&fdst[i * 32 + lane], ONES);

        // (c) consume loads via ballots, write packed word to smem
        if (r < T_ROWS) {
            uint32_t word = 0u;
            if (rowok) {
                uint32_t b0 = 0, b1 = 0, b2 = 0, b3 = 0;
#pragma unroll
                for (int k = 0; k < 8; ++k) {
                    const uint32_t t0 = __ballot_sync(0xFFFFFFFFu, v[k].x != 0.0f);
                    const uint32_t t1 = __ballot_sync(0xFFFFFFFFu, v[k].y != 0.0f);
                    const uint32_t t2 = __ballot_sync(0xFFFFFFFFu, v[k].z != 0.0f);
                    const uint32_t t3 = __ballot_sync(0xFFFFFFFFu, v[k].w != 0.0f);
                    if ((lane >> 2) == k) { b0 = t0; b1 = t1; b2 = t2; b3 = t3; }
                }
                const int s = (lane & 3) * 8;
                word = spread4(b0 >> s)
                     | (spread4(b1 >> s) << 1)
                     | (spread4(b2 >> s) << 2)
                     | (spread4(b3 >> s) << 3);
            }
            sbuf[0][r][1 + lane] = word;
        }
    }
    __syncthreads();

    // ---- 5 dilation iterations, ping-pong in smem ----
    int cur = 0;
#pragma unroll
    for (int it = 0; it < 5; ++it) {
        const int nxt = cur ^ 1;
#pragma unroll
        for (int base = 0; base < T_ROWS * WORDS; base += THREADS) {
            const int idx = base + tid;
            if (idx < T_ROWS * WORDS) {          // 2368 words
                const int r = idx >> 5;
                const int w = (idx & 31) + 1;
                const uint32_t c  = sbuf[cur][r][w];
                const uint32_t lw = sbuf[cur][r][w - 1];
                const uint32_t rw = sbuf[cur][r][w + 1];
                const uint32_t up = (r > 0)          ? sbuf[cur][r - 1][w] : 0u;
                const uint32_t dn = (r < T_ROWS - 1) ? sbuf[cur][r + 1][w] : 0u;
                sbuf[nxt][r][w] = c | up | dn
                                | (c << 1) | (lw >> 31)
                                | (c >> 1) | (rw << 31);
            }
        }
        __syncthreads();
        cur = nxt;
    }

    // ---- scatter zeros (~0.16% of pixels); block already filled its rows ----
#pragma unroll
    for (int q = 0; q < 4; ++q) {
        const int idx = q * THREADS + tid;       // 2048 words
        const int r   = idx >> 5;                // output row within tile
        const int w   = idx & 31;
        uint32_t z = ~sbuf[cur][HALO + r][w + 1];
        if (z) {
            float* orow = obase + (size_t)(r0 + r) * W_IMG + w * 32;
            do {
                const int b = __ffs(z) - 1;
                orow[b] = 0.0f;
                z &= z - 1u;
            } while (z);
        }
    }
}

extern "C" void kernel_launch(void* const* d_in, const int* in_sizes, int n_in,
                              void* d_out, int out_size) {
    const float* mask = (const float*)d_in[0];   // (16,1,1024,1024) f32, binary
    // d_in[1] = fixed Laplacian-cross weight, d_in[2] = iter_num (=5):
    // the op reduces exactly to 5 iterations of 4-connected binary dilation.
    float* out = (float*)d_out;

    dim3 grid(H_IMG / R_TILE, B_IMG);            // 16 x 16 = 256 blocks
    dilate_fused_kernel<<<grid, THREADS>>>(mask, out);
}